// round 7
// baseline (speedup 1.0000x reference)
#include <cuda_runtime.h>
#include <cuda_fp16.h>
#include <cstdint>

// ---------------------------------------------------------------------------
// CombinedHiddenEncoder — scratch lives in d_out; statics ~2.1 MB only.
//
// Folded algebra ((A·X)@W = A·(X@W)):
//   U1=W1@W3a, U2=W2@W3b, bq=b1@W3a+b2@W3b
//   R = h3 = A·( A·(F@U1 + C@U2) + bq ) + b3          (col-blocked by 32)
//   g = A·R (fp16), (mean|logvar) = g@[Wm|Wv]+bcat, z = noise*exp(.5lv)+mean
//
// d_out layout (O = float[9.6M]):
//   stage1 (×4 col-blocks): P=O[0:1.6M), Q=O[1.6M:3.2M), R=O[3.2M:9.6M)
//   stage2: g fp16 over O[0:3.2M)            (reads R — disjoint)
//   stage3: mean=O[3.2M:6.4M), lv=O[6.4M:9.6M) (reads g — R dead)
//   stage4: z=O[0:3.2M)                       (reads mean/lv/noise — g dead)
// ---------------------------------------------------------------------------

#define NN 50000
#define NE 600000
#define NB_SCAN 196          // ceil(50000/256)

// ------------------------- small device statics (~2.1 MB) ------------------
__device__ unsigned short g_src[NE];      // 1.2 MB (node ids < 65536)
__device__ int   g_cnt[NN];
__device__ int   g_off[NN + 1];
__device__ float g_dinv[NN];
__device__ int   g_bsum[256];
__device__ int   g_bpre[256];
__device__ float g_U1[256 * 128];         // W1@W3a
__device__ float g_U2[128 * 128];         // W2@W3b
__device__ float g_bq[128];               // b1@W3a + b2@W3b
__device__ float g_Wcat[128 * 128];       // [Wm|Wv]
__device__ float g_bcat[128];             // [bm|bv]
__device__ int   g_is64;

// ------------------------- CSR build ---------------------------------------
__global__ void zero_detect_kernel(const int* __restrict__ ei32) {
    int i = blockIdx.x * blockDim.x + threadIdx.x;
    if (i < NN) g_cnt[i] = 0;
    if (i == 0) {   // int64 edge_index => odd 32-bit words all zero (ids < 2^31)
        int nz = 0;
        for (int k = 0; k < 512; k++) nz |= ei32[2 * k + 1];
        g_is64 = (nz == 0) ? 1 : 0;
    }
}

__device__ __forceinline__ int edge_val(const void* ei, int idx) {
    if (g_is64) return (int)((const long long*)ei)[idx];
    return ((const int*)ei)[idx];
}

__global__ void count_deg_kernel(const void* __restrict__ ei) {
    int e = blockIdx.x * blockDim.x + threadIdx.x;
    if (e >= NE) return;
    atomicAdd(&g_cnt[edge_val(ei, NE + e)], 1);
}

// inclusive scan of cnt into g_off; also dinv
__global__ void scan1_kernel() {
    __shared__ int s[256];
    int tid = threadIdx.x;
    int i = blockIdx.x * 256 + tid;
    int v = (i < NN) ? g_cnt[i] : 0;
    if (i < NN) g_dinv[i] = rsqrtf((float)(v + 1));  // +1 self loop
    s[tid] = v;
    __syncthreads();
    for (int off = 1; off < 256; off <<= 1) {
        int t = (tid >= off) ? s[tid - off] : 0;
        __syncthreads();
        s[tid] += t;
        __syncthreads();
    }
    if (i < NN) g_off[i] = s[tid];
    if (tid == 255) g_bsum[blockIdx.x] = s[255];
}

__global__ void scan2_kernel() {
    __shared__ int s[256];
    int tid = threadIdx.x;
    int v = (tid < NB_SCAN) ? g_bsum[tid] : 0;
    s[tid] = v;
    __syncthreads();
    for (int off = 1; off < 256; off <<= 1) {
        int t = (tid >= off) ? s[tid - off] : 0;
        __syncthreads();
        s[tid] += t;
        __syncthreads();
    }
    g_bpre[tid] = s[tid] - v;   // exclusive
}

__global__ void scan3_kernel() {
    int tid = threadIdx.x;
    int i = blockIdx.x * 256 + tid;
    if (i < NN) {
        g_off[i] = g_off[i] - g_cnt[i] + g_bpre[blockIdx.x];  // exclusive start
        g_cnt[i] = 0;
    }
    if (i == 0) g_off[NN] = NE;
}

__global__ void scatter_kernel(const void* __restrict__ ei) {
    int e = blockIdx.x * blockDim.x + threadIdx.x;
    if (e >= NE) return;
    int s = edge_val(ei, e);
    int d = edge_val(ei, NE + e);
    int p = g_off[d] + atomicAdd(&g_cnt[d], 1);
    g_src[p] = (unsigned short)s;
}

// ------------------------- weight folding ----------------------------------
// U1[i][j] = sum_k W1[i][k]*W3[k][j];  U2[i][j] = sum_k W2[i][k]*W3[128+k][j]
// bq[j] = sum_k b1[k]*W3[k][j] + b2[k]*W3[128+k][j];  Wcat/bcat = [Wm|Wv],[bm|bv]
__global__ void prep_kernel(const float* __restrict__ W1, const float* __restrict__ W2,
                            const float* __restrict__ W3, const float* __restrict__ b1,
                            const float* __restrict__ b2,
                            const float* __restrict__ Wm, const float* __restrict__ Wv,
                            const float* __restrict__ bm, const float* __restrict__ bv) {
    int idx = blockIdx.x * blockDim.x + threadIdx.x;
    if (idx < 256 * 128) {                       // U1
        int i = idx >> 7, j = idx & 127;
        float a = 0.f;
        for (int k = 0; k < 128; k++) a += W1[i * 128 + k] * W3[k * 128 + j];
        g_U1[idx] = a;
    } else if (idx < 256 * 128 + 128 * 128) {    // U2
        int t = idx - 256 * 128;
        int i = t >> 7, j = t & 127;
        float a = 0.f;
        for (int k = 0; k < 128; k++) a += W2[i * 128 + k] * W3[(128 + k) * 128 + j];
        g_U2[t] = a;
    } else if (idx < 256 * 128 + 128 * 128 + 128) {   // bq
        int j = idx - 256 * 128 - 128 * 128;
        float a = 0.f;
        for (int k = 0; k < 128; k++)
            a += b1[k] * W3[k * 128 + j] + b2[k] * W3[(128 + k) * 128 + j];
        g_bq[j] = a;
    } else if (idx < 256 * 128 + 128 * 128 + 128 + 128 * 128) {   // Wcat
        int t = idx - 256 * 128 - 128 * 128 - 128;
        int k = t >> 7, n = t & 127;
        g_Wcat[t] = (n < 64) ? Wm[k * 64 + n] : Wv[k * 64 + (n - 64)];
    } else if (idx < 256 * 128 + 128 * 128 + 128 + 128 * 128 + 128) {  // bcat
        int n = idx - 256 * 128 - 128 * 128 - 128 - 128 * 128;
        g_bcat[n] = (n < 64) ? bm[n] : bv[n - 64];
    }
}

// ------------------------- GEMM-P: P = F@U1[:,c:c+32] + C@U2[:,c:c+32] -----
// BM=128, BN=32; 256 threads; thread tile 4x4.
__global__ __launch_bounds__(256) void gemmP_kernel(
    const float* __restrict__ F, const float* __restrict__ C,
    float* __restrict__ P, int c)
{
    __shared__ float As[16][128];
    __shared__ float Bs[16][32];
    int tid = threadIdx.x;
    int tx = tid & 7, ty = tid >> 3;       // 8 x 32
    int rowBase = blockIdx.x * 128;
    float acc[4][4];
#pragma unroll
    for (int i = 0; i < 4; i++)
#pragma unroll
        for (int j = 0; j < 4; j++) acc[i][j] = 0.f;

#pragma unroll
    for (int ph = 0; ph < 2; ph++) {
        const float* A = ph ? C : F;
        const float* B = ph ? g_U2 : g_U1;
        int ldA = ph ? 128 : 256;
        int K   = ph ? 128 : 256;
        for (int k0 = 0; k0 < K; k0 += 16) {
#pragma unroll
            for (int l = 0; l < 2; l++) {      // A tile transposed: As[k][row]
                int idx = tid * 2 + l;
                int r = idx >> 2, c4 = idx & 3;
                float4 v = make_float4(0.f, 0.f, 0.f, 0.f);
                int gr = rowBase + r;
                if (gr < NN) v = *(const float4*)&A[(size_t)gr * ldA + k0 + c4 * 4];
                As[c4 * 4 + 0][r] = v.x;
                As[c4 * 4 + 1][r] = v.y;
                As[c4 * 4 + 2][r] = v.z;
                As[c4 * 4 + 3][r] = v.w;
            }
#pragma unroll
            for (int l = 0; l < 2; l++) {      // B tile 16x32
                int idx = tid + l * 256;
                int r = idx >> 5, n = idx & 31;
                Bs[r][n] = B[(size_t)(k0 + r) * 128 + c + n];
            }
            __syncthreads();
#pragma unroll
            for (int k = 0; k < 16; k++) {
                float4 a = *(const float4*)&As[k][ty * 4];
                float4 b = *(const float4*)&Bs[k][tx * 4];
                acc[0][0] += a.x * b.x; acc[0][1] += a.x * b.y; acc[0][2] += a.x * b.z; acc[0][3] += a.x * b.w;
                acc[1][0] += a.y * b.x; acc[1][1] += a.y * b.y; acc[1][2] += a.y * b.z; acc[1][3] += a.y * b.w;
                acc[2][0] += a.z * b.x; acc[2][1] += a.z * b.y; acc[2][2] += a.z * b.z; acc[2][3] += a.z * b.w;
                acc[3][0] += a.w * b.x; acc[3][1] += a.w * b.y; acc[3][2] += a.w * b.z; acc[3][3] += a.w * b.w;
            }
            __syncthreads();
        }
    }
#pragma unroll
    for (int i = 0; i < 4; i++) {
        int gr = rowBase + ty * 4 + i;
        if (gr < NN)
            *(float4*)&P[(size_t)gr * 32 + tx * 4] =
                make_float4(acc[i][0], acc[i][1], acc[i][2], acc[i][3]);
    }
}

// ------------------------- agg, width 32 (warp per node) -------------------
// out[node*outStride + outOff + lane] = di*(sum_j dinv_j*in[j*32+lane] + di*in[node*32+lane]) + bias
// biasExt==null -> bias = g_bq[c+lane], else biasExt[c+lane]
__global__ __launch_bounds__(256) void agg32_kernel(
    const float* __restrict__ in, float* __restrict__ out,
    int outStride, int outOff, const float* __restrict__ biasExt, int c)
{
    int node = (blockIdx.x * blockDim.x + threadIdx.x) >> 5;
    if (node >= NN) return;
    int lane = threadIdx.x & 31;
    float di = g_dinv[node];
    float acc = di * in[(size_t)node * 32 + lane];
    int s = g_off[node], e = g_off[node + 1];
    for (int k = s; k < e; k++) {
        int j = g_src[k];
        acc += g_dinv[j] * in[(size_t)j * 32 + lane];
    }
    float b = biasExt ? biasExt[c + lane] : g_bq[c + lane];
    out[(size_t)node * outStride + outOff + lane] = acc * di + b;
}

// ------------------------- agg, width 128, fp16 output ---------------------
// g = A·R (no bias; bcat added in the final GEMM)
__global__ __launch_bounds__(256) void aggG_kernel(
    const float* __restrict__ R, __half* __restrict__ G)
{
    int node = (blockIdx.x * blockDim.x + threadIdx.x) >> 5;
    if (node >= NN) return;
    int lane = threadIdx.x & 31;
    float di = g_dinv[node];
    float4 t = ((const float4*)(R + (size_t)node * 128))[lane];
    float4 acc = make_float4(t.x * di, t.y * di, t.z * di, t.w * di);
    int s = g_off[node], e = g_off[node + 1];
    for (int k = s; k < e; k++) {
        int j = g_src[k];
        float w = g_dinv[j];
        float4 r = ((const float4*)(R + (size_t)j * 128))[lane];
        acc.x += r.x * w; acc.y += r.y * w; acc.z += r.z * w; acc.w += r.w * w;
    }
    __half* gp = G + (size_t)node * 128 + lane * 4;
    ((__half2*)gp)[0] = __floats2half2_rn(acc.x * di, acc.y * di);
    ((__half2*)gp)[1] = __floats2half2_rn(acc.z * di, acc.w * di);
}

// ------------------------- GEMM-MV: (mean|lv) = g@Wcat + bcat --------------
// BM=128, BN=128, BK=16; A is fp16. Output split: cols 0-63 -> mean region,
// cols 64-127 -> logvar region.
__global__ __launch_bounds__(256) void gemmMV_kernel(
    const __half* __restrict__ G, float* __restrict__ O)
{
    __shared__ float As[16][128];
    __shared__ float Bs[16][128];
    int tid = threadIdx.x;
    int tx = tid & 15, ty = tid >> 4;
    int rowBase = blockIdx.x * 128;
    float acc[8][8];
#pragma unroll
    for (int i = 0; i < 8; i++)
#pragma unroll
        for (int j = 0; j < 8; j++) acc[i][j] = 0.f;

    for (int k0 = 0; k0 < 128; k0 += 16) {
        {   // A tile (halves): each thread one 16B load = 8 halves
            int r = tid >> 1;
            int hb = (tid & 1) * 8;
            int gr = rowBase + r;
            uint4 u = make_uint4(0u, 0u, 0u, 0u);
            if (gr < NN) u = *(const uint4*)&G[(size_t)gr * 128 + k0 + hb];
            const __half2* hp = (const __half2*)&u;
#pragma unroll
            for (int q = 0; q < 4; q++) {
                float2 f = __half22float2(hp[q]);
                As[hb + q * 2 + 0][r] = f.x;
                As[hb + q * 2 + 1][r] = f.y;
            }
        }
#pragma unroll
        for (int l = 0; l < 2; l++) {          // B tile from g_Wcat
            int idx = tid + l * 256;
            int r = idx >> 5, c4 = idx & 31;
            *(float4*)&Bs[r][c4 * 4] =
                *(const float4*)&g_Wcat[(size_t)(k0 + r) * 128 + c4 * 4];
        }
        __syncthreads();
#pragma unroll
        for (int k = 0; k < 16; k++) {
            float4 a0 = *(const float4*)&As[k][ty * 8];
            float4 a1 = *(const float4*)&As[k][ty * 8 + 4];
            float4 b0 = *(const float4*)&Bs[k][tx * 8];
            float4 b1 = *(const float4*)&Bs[k][tx * 8 + 4];
#define MV_ROW(i, av)                                                         \
            acc[i][0] += (av) * b0.x; acc[i][1] += (av) * b0.y;               \
            acc[i][2] += (av) * b0.z; acc[i][3] += (av) * b0.w;               \
            acc[i][4] += (av) * b1.x; acc[i][5] += (av) * b1.y;               \
            acc[i][6] += (av) * b1.z; acc[i][7] += (av) * b1.w;
            MV_ROW(0, a0.x) MV_ROW(1, a0.y) MV_ROW(2, a0.z) MV_ROW(3, a0.w)
            MV_ROW(4, a1.x) MV_ROW(5, a1.y) MV_ROW(6, a1.z) MV_ROW(7, a1.w)
#undef MV_ROW
        }
        __syncthreads();
    }
    // epilogue: bias + split store (tx<8 -> mean, tx>=8 -> logvar)
#pragma unroll
    for (int i = 0; i < 8; i++) {
        int gr = rowBase + ty * 8 + i;
        if (gr < NN) {
            int n0 = tx * 8;
            float* dst = (n0 < 64)
                ? &O[3200000 + (size_t)gr * 64 + n0]
                : &O[6400000 + (size_t)gr * 64 + (n0 - 64)];
#pragma unroll
            for (int h = 0; h < 2; h++) {
                float4 v = make_float4(acc[i][h * 4 + 0] + g_bcat[n0 + h * 4 + 0],
                                       acc[i][h * 4 + 1] + g_bcat[n0 + h * 4 + 1],
                                       acc[i][h * 4 + 2] + g_bcat[n0 + h * 4 + 2],
                                       acc[i][h * 4 + 3] + g_bcat[n0 + h * 4 + 3]);
                *(float4*)(dst + h * 4) = v;
            }
        }
    }
}

// ------------------------- reparameterize ----------------------------------
__global__ void reparam_kernel(const float* __restrict__ noise, float* __restrict__ O) {
    int i = blockIdx.x * blockDim.x + threadIdx.x;
    if (i >= 3200000) return;
    float lv = O[6400000 + i];
    O[i] = noise[i] * expf(0.5f * lv) + O[3200000 + i];
}

// ------------------------- host launcher -----------------------------------
extern "C" void kernel_launch(void* const* d_in, const int* in_sizes, int n_in,
                              void* d_out, int out_size)
{
    const float* feature   = (const float*)d_in[0];
    const float* condition = (const float*)d_in[1];
    const void*  edge_ix   = d_in[2];
    const float* noise     = (const float*)d_in[3];
    const float* W1 = (const float*)d_in[4];
    const float* b1 = (const float*)d_in[5];
    const float* W2 = (const float*)d_in[6];
    const float* b2 = (const float*)d_in[7];
    const float* W3 = (const float*)d_in[8];
    const float* b3 = (const float*)d_in[9];
    const float* Wm = (const float*)d_in[10];
    const float* bm = (const float*)d_in[11];
    const float* Wv = (const float*)d_in[12];
    const float* bv = (const float*)d_in[13];
    float* O = (float*)d_out;

    float* P = O;                 // 50k x 32
    float* Q = O + 1600000;       // 50k x 32
    float* R = O + 3200000;       // 50k x 128
    __half* G = (__half*)O;       // 50k x 128 fp16 over [0 : 3.2M floats)

    const int TB = 256;
    const int gN  = (NN + TB - 1) / TB;      // 196
    const int gE  = (NE + TB - 1) / TB;      // 2344
    const int gG  = (NN + 127) / 128;        // 391
    const int gW  = (NN * 32) / TB;          // 6250 (warp per node, exact)
    const int gPrep = (256*128 + 128*128 + 128 + 128*128 + 128 + TB - 1) / TB;

    // CSR build + weight folding
    zero_detect_kernel<<<gN, TB>>>((const int*)edge_ix);
    count_deg_kernel<<<gE, TB>>>(edge_ix);
    scan1_kernel<<<NB_SCAN, 256>>>();
    scan2_kernel<<<1, 256>>>();
    scan3_kernel<<<NB_SCAN, 256>>>();
    scatter_kernel<<<gE, TB>>>(edge_ix);
    prep_kernel<<<gPrep, TB>>>(W1, W2, W3, b1, b2, Wm, Wv, bm, bv);

    // R = h3, 32 columns at a time
    for (int c = 0; c < 128; c += 32) {
        gemmP_kernel<<<gG, TB>>>(feature, condition, P, c);
        agg32_kernel<<<gW, TB>>>(P, Q, 32, 0, nullptr, c);   // Q = A·P + bq[c..]
        agg32_kernel<<<gW, TB>>>(Q, R, 128, c, b3, c);       // R[:,c..] = A·Q + b3[c..]
    }

    // g = A·R (fp16) ; (mean|logvar) = g@Wcat + bcat ; z = reparam
    aggG_kernel<<<gW, TB>>>(R, G);
    gemmMV_kernel<<<gG, TB>>>(G, O);
    reparam_kernel<<<(3200000 + TB - 1) / TB, TB>>>(noise, O);
}

// round 8
// speedup vs baseline: 1.3887x; 1.3887x over previous
#include <cuda_runtime.h>
#include <cuda_fp16.h>
#include <cstdint>

// ---------------------------------------------------------------------------
// CombinedHiddenEncoder — R7: FFMA2 packed GEMMs, 64-wide fp16 col-blocks,
// reparam fused into final GEMM epilogue (interleaved [Wm|Wv]).
//
// Folded algebra ((A·X)@W = A·(X@W)):
//   U1=W1@W3a, U2=W2@W3b, bq=b1@W3a+b2@W3b
//   R = h3 = A·( A·(F@U1 + C@U2) + bq ) + b3          (col-blocked by 64)
//   G = A·R (fp16), (mean|lv) = G@[Wm|Wv]int + bcat, z fused in epilogue
//
// d_out layout (O = float[9.6M]):
//   stage1 (×2 col-blocks): P fp16 = O[0:1.6M), Q fp16 = O[1.6M:3.2M),
//                           R fp32 = O[3.2M:9.6M)
//   stage2: G fp16 over O[0:3.2M)              (reads R — disjoint)
//   stage3: mean=O[3.2M:6.4M), lv=O[6.4M:9.6M) (reads G; R dead)
//           z=O[0:3.2M) fused (overwrites own G rows post-consumption)
// ---------------------------------------------------------------------------

#define NN 50000
#define NE 600000
#define NB_SCAN 196          // ceil(50000/256)
typedef unsigned long long ull;

// ------------------------- small device statics (~2.1 MB) ------------------
__device__ unsigned short g_src[NE];      // node ids < 65536
__device__ int   g_cnt[NN];
__device__ int   g_off[NN + 1];
__device__ float g_dinv[NN];
__device__ int   g_bsum[256];
__device__ int   g_bpre[256];
__device__ float g_U1[256 * 128];         // W1@W3a
__device__ float g_U2[128 * 128];         // W2@W3b
__device__ float g_bq[128];               // b1@W3a + b2@W3b
__device__ float g_Wcat[128 * 128];       // [Wm|Wv] column-interleaved
__device__ float g_bcat[128];             // [bm|bv] interleaved
__device__ int   g_is64;

// ------------------------- f32x2 helpers -----------------------------------
__device__ __forceinline__ ull pk2(float x, float y) {
    ull r; asm("mov.b64 %0, {%1, %2};" : "=l"(r) : "f"(x), "f"(y)); return r;
}
__device__ __forceinline__ void upk2(ull v, float& x, float& y) {
    asm("mov.b64 {%0, %1}, %2;" : "=f"(x), "=f"(y) : "l"(v));
}
__device__ __forceinline__ void ffma2(ull& d, ull a, ull b) {
    asm("fma.rn.f32x2 %0, %1, %2, %0;" : "+l"(d) : "l"(a), "l"(b));
}

// ------------------------- CSR build ---------------------------------------
__global__ void zero_detect_kernel(const int* __restrict__ ei32) {
    int i = blockIdx.x * blockDim.x + threadIdx.x;
    if (i < NN) g_cnt[i] = 0;
    if (i == 0) {   // int64 edge_index => odd 32-bit words all zero (ids < 2^31)
        int nz = 0;
        for (int k = 0; k < 512; k++) nz |= ei32[2 * k + 1];
        g_is64 = (nz == 0) ? 1 : 0;
    }
}

__device__ __forceinline__ int edge_val(const void* ei, int idx) {
    if (g_is64) return (int)((const long long*)ei)[idx];
    return ((const int*)ei)[idx];
}

__global__ void count_deg_kernel(const void* __restrict__ ei) {
    int e = blockIdx.x * blockDim.x + threadIdx.x;
    if (e >= NE) return;
    atomicAdd(&g_cnt[edge_val(ei, NE + e)], 1);
}

__global__ void scan1_kernel() {
    __shared__ int s[256];
    int tid = threadIdx.x;
    int i = blockIdx.x * 256 + tid;
    int v = (i < NN) ? g_cnt[i] : 0;
    if (i < NN) g_dinv[i] = rsqrtf((float)(v + 1));  // +1 self loop
    s[tid] = v;
    __syncthreads();
    for (int off = 1; off < 256; off <<= 1) {
        int t = (tid >= off) ? s[tid - off] : 0;
        __syncthreads();
        s[tid] += t;
        __syncthreads();
    }
    if (i < NN) g_off[i] = s[tid];
    if (tid == 255) g_bsum[blockIdx.x] = s[255];
}

__global__ void scan2_kernel() {
    __shared__ int s[256];
    int tid = threadIdx.x;
    int v = (tid < NB_SCAN) ? g_bsum[tid] : 0;
    s[tid] = v;
    __syncthreads();
    for (int off = 1; off < 256; off <<= 1) {
        int t = (tid >= off) ? s[tid - off] : 0;
        __syncthreads();
        s[tid] += t;
        __syncthreads();
    }
    g_bpre[tid] = s[tid] - v;   // exclusive
}

__global__ void scan3_kernel() {
    int tid = threadIdx.x;
    int i = blockIdx.x * 256 + tid;
    if (i < NN) {
        g_off[i] = g_off[i] - g_cnt[i] + g_bpre[blockIdx.x];
        g_cnt[i] = 0;
    }
    if (i == 0) g_off[NN] = NE;
}

__global__ void scatter_kernel(const void* __restrict__ ei) {
    int e = blockIdx.x * blockDim.x + threadIdx.x;
    if (e >= NE) return;
    int s = edge_val(ei, e);
    int d = edge_val(ei, NE + e);
    int p = g_off[d] + atomicAdd(&g_cnt[d], 1);
    g_src[p] = (unsigned short)s;
}

// ------------------------- weight folding ----------------------------------
__global__ void prep_kernel(const float* __restrict__ W1, const float* __restrict__ W2,
                            const float* __restrict__ W3, const float* __restrict__ b1,
                            const float* __restrict__ b2,
                            const float* __restrict__ Wm, const float* __restrict__ Wv,
                            const float* __restrict__ bm, const float* __restrict__ bv) {
    int idx = blockIdx.x * blockDim.x + threadIdx.x;
    if (idx < 256 * 128) {                       // U1 = W1@W3[0:128]
        int i = idx >> 7, j = idx & 127;
        float a = 0.f;
        for (int k = 0; k < 128; k++) a += W1[i * 128 + k] * W3[k * 128 + j];
        g_U1[idx] = a;
    } else if (idx < 256 * 128 + 128 * 128) {    // U2 = W2@W3[128:256]
        int t = idx - 256 * 128;
        int i = t >> 7, j = t & 127;
        float a = 0.f;
        for (int k = 0; k < 128; k++) a += W2[i * 128 + k] * W3[(128 + k) * 128 + j];
        g_U2[t] = a;
    } else if (idx < 256 * 128 + 128 * 128 + 128) {   // bq
        int j = idx - 256 * 128 - 128 * 128;
        float a = 0.f;
        for (int k = 0; k < 128; k++)
            a += b1[k] * W3[k * 128 + j] + b2[k] * W3[(128 + k) * 128 + j];
        g_bq[j] = a;
    } else if (idx < 256 * 128 + 128 * 128 + 128 + 128 * 128) {   // Wcat interleaved
        int t = idx - 256 * 128 - 128 * 128 - 128;
        int k = t >> 7, n = t & 127;
        g_Wcat[t] = (n & 1) ? Wv[k * 64 + (n >> 1)] : Wm[k * 64 + (n >> 1)];
    } else if (idx < 256 * 128 + 128 * 128 + 128 + 128 * 128 + 128) {  // bcat
        int n = idx - 256 * 128 - 128 * 128 - 128 - 128 * 128;
        g_bcat[n] = (n & 1) ? bv[n >> 1] : bm[n >> 1];
    }
}

// ------------------------- GEMM-P: P(fp16) = [F|C] @ [U1;U2][:,c:c+64] -----
// BM=128, BN=64, 256 threads; thread tile 8 rows x 4 cols; FFMA2 row-pairs.
__global__ __launch_bounds__(256) void gemmP_kernel(
    const float* __restrict__ F, const float* __restrict__ C,
    __half* __restrict__ P, int c)
{
    __shared__ float As[16][128];
    __shared__ float Bs[16][64];
    int tid = threadIdx.x;
    int tx = tid & 15, ty = tid >> 4;
    int rowBase = blockIdx.x * 128;
    ull acc[4][4];     // [row-pair p][col cc]: rows (ty*8+2p, +1), col tx*4+cc
#pragma unroll
    for (int p = 0; p < 4; p++)
#pragma unroll
        for (int q = 0; q < 4; q++) acc[p][q] = 0ull;

#pragma unroll
    for (int ph = 0; ph < 2; ph++) {
        const float* A = ph ? C : F;
        const float* B = ph ? g_U2 : g_U1;
        int ldA = ph ? 128 : 256;
        int K   = ph ? 128 : 256;
        for (int k0 = 0; k0 < K; k0 += 16) {
#pragma unroll
            for (int l = 0; l < 2; l++) {      // A tile transposed: As[k][row]
                int idx = tid * 2 + l;
                int r = idx >> 2, c4 = idx & 3;
                float4 v = make_float4(0.f, 0.f, 0.f, 0.f);
                int gr = rowBase + r;
                if (gr < NN) v = *(const float4*)&A[(size_t)gr * ldA + k0 + c4 * 4];
                As[c4 * 4 + 0][r] = v.x;
                As[c4 * 4 + 1][r] = v.y;
                As[c4 * 4 + 2][r] = v.z;
                As[c4 * 4 + 3][r] = v.w;
            }
            {                                   // B tile 16x64 (1 float4/thread)
                int r = tid >> 4, n4 = tid & 15;
                *(float4*)&Bs[r][n4 * 4] =
                    *(const float4*)&B[(size_t)(k0 + r) * 128 + c + n4 * 4];
            }
            __syncthreads();
#pragma unroll
            for (int k = 0; k < 16; k++) {
                const ull* ap = (const ull*)&As[k][ty * 8];
                ull a0 = ap[0], a1 = ap[1], a2 = ap[2], a3 = ap[3];
                float4 b = *(const float4*)&Bs[k][tx * 4];
                ull s0 = pk2(b.x, b.x), s1 = pk2(b.y, b.y);
                ull s2 = pk2(b.z, b.z), s3 = pk2(b.w, b.w);
                ffma2(acc[0][0], a0, s0); ffma2(acc[0][1], a0, s1);
                ffma2(acc[0][2], a0, s2); ffma2(acc[0][3], a0, s3);
                ffma2(acc[1][0], a1, s0); ffma2(acc[1][1], a1, s1);
                ffma2(acc[1][2], a1, s2); ffma2(acc[1][3], a1, s3);
                ffma2(acc[2][0], a2, s0); ffma2(acc[2][1], a2, s1);
                ffma2(acc[2][2], a2, s2); ffma2(acc[2][3], a2, s3);
                ffma2(acc[3][0], a3, s0); ffma2(acc[3][1], a3, s1);
                ffma2(acc[3][2], a3, s2); ffma2(acc[3][3], a3, s3);
            }
            __syncthreads();
        }
    }
    // epilogue: fp16 store, 4 cols per row
#pragma unroll
    for (int p = 0; p < 4; p++) {
#pragma unroll
        for (int q = 0; q < 2; q++) {
            int gr = rowBase + ty * 8 + p * 2 + q;
            if (gr < NN) {
                float v0, v1, v2, v3, d0, d1;
                upk2(acc[p][0], v0, d0); if (q) v0 = d0;
                upk2(acc[p][1], v1, d0); if (q) v1 = d0;
                upk2(acc[p][2], v2, d0); if (q) v2 = d0;
                upk2(acc[p][3], v3, d1); if (q) v3 = d1;
                __half2* dst = (__half2*)&P[(size_t)gr * 64 + tx * 4];
                dst[0] = __floats2half2_rn(v0, v1);
                dst[1] = __floats2half2_rn(v2, v3);
            }
        }
    }
}

// ------------------------- agg width-64 (warp per node) --------------------
// OUTF=0: fp16 out (Q, stride 64, bias g_bq[c..]); OUTF=1: fp32 out
// (R, stride 128, offset c, bias b3[c..]).
template <int OUTF>
__global__ __launch_bounds__(256) void agg64_kernel(
    const __half* __restrict__ in, void* __restrict__ outv,
    const float* __restrict__ biasExt, int c)
{
    int node = (blockIdx.x * blockDim.x + threadIdx.x) >> 5;
    if (node >= NN) return;
    int lane = threadIdx.x & 31;
    float di = g_dinv[node];
    float2 t = __half22float2(*(const __half2*)&in[(size_t)node * 64 + lane * 2]);
    float ax = di * t.x, ay = di * t.y;
    int s = g_off[node], e = g_off[node + 1];
    for (int k = s; k < e; k++) {
        int j = g_src[k];
        float w = g_dinv[j];
        float2 r = __half22float2(*(const __half2*)&in[(size_t)j * 64 + lane * 2]);
        ax += w * r.x; ay += w * r.y;
    }
    float b0 = biasExt ? biasExt[c + lane * 2]     : g_bq[c + lane * 2];
    float b1 = biasExt ? biasExt[c + lane * 2 + 1] : g_bq[c + lane * 2 + 1];
    if (OUTF) {
        float* out = (float*)outv;
        *(float2*)&out[(size_t)node * 128 + c + lane * 2] =
            make_float2(ax * di + b0, ay * di + b1);
    } else {
        __half* out = (__half*)outv;
        *(__half2*)&out[(size_t)node * 64 + lane * 2] =
            __floats2half2_rn(ax * di + b0, ay * di + b1);
    }
}

// ------------------------- agg width-128: G = A·R (fp16) -------------------
__global__ __launch_bounds__(256) void aggG_kernel(
    const float* __restrict__ R, __half* __restrict__ G)
{
    int node = (blockIdx.x * blockDim.x + threadIdx.x) >> 5;
    if (node >= NN) return;
    int lane = threadIdx.x & 31;
    float di = g_dinv[node];
    float4 t = ((const float4*)(R + (size_t)node * 128))[lane];
    float4 acc = make_float4(t.x * di, t.y * di, t.z * di, t.w * di);
    int s = g_off[node], e = g_off[node + 1];
    for (int k = s; k < e; k++) {
        int j = g_src[k];
        float w = g_dinv[j];
        float4 r = ((const float4*)(R + (size_t)j * 128))[lane];
        acc.x += r.x * w; acc.y += r.y * w; acc.z += r.z * w; acc.w += r.w * w;
    }
    __half* gp = G + (size_t)node * 128 + lane * 4;
    ((__half2*)gp)[0] = __floats2half2_rn(acc.x * di, acc.y * di);
    ((__half2*)gp)[1] = __floats2half2_rn(acc.z * di, acc.w * di);
}

// ------------------------- GEMM-MV + fused reparam -------------------------
// (mean|lv interleaved) = G@Wcat + bcat; z = noise*exp(.5lv)+mean in epilogue.
// BM=128, BN=128, BK=16; A fp16; acc packed row-pairs.
__global__ __launch_bounds__(256) void gemmMV_kernel(
    const __half* __restrict__ G, const float* __restrict__ noise,
    float* __restrict__ O)
{
    __shared__ float As[16][128];
    __shared__ float Bs[16][128];
    int tid = threadIdx.x;
    int tx = tid & 15, ty = tid >> 4;
    int rowBase = blockIdx.x * 128;
    ull acc[4][8];
#pragma unroll
    for (int p = 0; p < 4; p++)
#pragma unroll
        for (int q = 0; q < 8; q++) acc[p][q] = 0ull;

    for (int k0 = 0; k0 < 128; k0 += 16) {
        {   // A tile: 2 threads per row, 8 halfs each, transposed to As[k][r]
            int r = tid >> 1;
            int hb = (tid & 1) * 8;
            int gr = rowBase + r;
            uint4 u = make_uint4(0u, 0u, 0u, 0u);
            if (gr < NN) u = *(const uint4*)&G[(size_t)gr * 128 + k0 + hb];
            const __half2* hp = (const __half2*)&u;
#pragma unroll
            for (int q = 0; q < 4; q++) {
                float2 f = __half22float2(hp[q]);
                As[hb + q * 2 + 0][r] = f.x;
                As[hb + q * 2 + 1][r] = f.y;
            }
        }
#pragma unroll
        for (int l = 0; l < 2; l++) {          // B tile
            int idx = tid + l * 256;
            int r = idx >> 5, c4 = idx & 31;
            *(float4*)&Bs[r][c4 * 4] =
                *(const float4*)&g_Wcat[(size_t)(k0 + r) * 128 + c4 * 4];
        }
        __syncthreads();
#pragma unroll
        for (int k = 0; k < 16; k++) {
            const ull* ap = (const ull*)&As[k][ty * 8];
            ull a0 = ap[0], a1 = ap[1], a2 = ap[2], a3 = ap[3];
            float4 b0 = *(const float4*)&Bs[k][tx * 8];
            float4 b1 = *(const float4*)&Bs[k][tx * 8 + 4];
            ull s0 = pk2(b0.x, b0.x), s1 = pk2(b0.y, b0.y);
            ull s2 = pk2(b0.z, b0.z), s3 = pk2(b0.w, b0.w);
            ull s4 = pk2(b1.x, b1.x), s5 = pk2(b1.y, b1.y);
            ull s6 = pk2(b1.z, b1.z), s7 = pk2(b1.w, b1.w);
#pragma unroll
            for (int p = 0; p < 4; p++) {
                ull a = (p == 0) ? a0 : (p == 1) ? a1 : (p == 2) ? a2 : a3;
                ffma2(acc[p][0], a, s0); ffma2(acc[p][1], a, s1);
                ffma2(acc[p][2], a, s2); ffma2(acc[p][3], a, s3);
                ffma2(acc[p][4], a, s4); ffma2(acc[p][5], a, s5);
                ffma2(acc[p][6], a, s6); ffma2(acc[p][7], a, s7);
            }
        }
        __syncthreads();
    }
    // epilogue: cols tx*8+2j = mean latent L=tx*4+j, +1 = logvar; fuse reparam.
    int n0 = tx * 8;
#pragma unroll
    for (int p = 0; p < 4; p++) {
#pragma unroll
        for (int q = 0; q < 2; q++) {
            int gr = rowBase + ty * 8 + p * 2 + q;
            if (gr < NN) {
                float4 mean, lv;
                float lo, hi;
#define GETV(j, mdst, ldst)                                                   \
                upk2(acc[p][2*(j)],   lo, hi); mdst = (q ? hi : lo) + g_bcat[n0 + 2*(j)]; \
                upk2(acc[p][2*(j)+1], lo, hi); ldst = (q ? hi : lo) + g_bcat[n0 + 2*(j)+1];
                GETV(0, mean.x, lv.x) GETV(1, mean.y, lv.y)
                GETV(2, mean.z, lv.z) GETV(3, mean.w, lv.w)
#undef GETV
                float4 nz = *(const float4*)&noise[(size_t)gr * 64 + tx * 4];
                float4 z;
                z.x = nz.x * expf(0.5f * lv.x) + mean.x;
                z.y = nz.y * expf(0.5f * lv.y) + mean.y;
                z.z = nz.z * expf(0.5f * lv.z) + mean.z;
                z.w = nz.w * expf(0.5f * lv.w) + mean.w;
                size_t o = (size_t)gr * 64 + tx * 4;
                *(float4*)&O[o] = z;                    // over own (dead) G rows
                *(float4*)&O[3200000 + o] = mean;
                *(float4*)&O[6400000 + o] = lv;
            }
        }
    }
}

// ------------------------- host launcher -----------------------------------
extern "C" void kernel_launch(void* const* d_in, const int* in_sizes, int n_in,
                              void* d_out, int out_size)
{
    const float* feature   = (const float*)d_in[0];
    const float* condition = (const float*)d_in[1];
    const void*  edge_ix   = d_in[2];
    const float* noise     = (const float*)d_in[3];
    const float* W1 = (const float*)d_in[4];
    const float* b1 = (const float*)d_in[5];
    const float* W2 = (const float*)d_in[6];
    const float* b2 = (const float*)d_in[7];
    const float* W3 = (const float*)d_in[8];
    const float* b3 = (const float*)d_in[9];
    const float* Wm = (const float*)d_in[10];
    const float* bm = (const float*)d_in[11];
    const float* Wv = (const float*)d_in[12];
    const float* bv = (const float*)d_in[13];
    float* O = (float*)d_out;

    __half* P = (__half*)O;               // 50k x 64 fp16  [0 : 1.6M floats)
    __half* Q = (__half*)(O + 1600000);   // 50k x 64 fp16  [1.6M : 3.2M)
    float*  R = O + 3200000;              // 50k x 128 fp32 [3.2M : 9.6M)
    __half* G = (__half*)O;               // 50k x 128 fp16 [0 : 3.2M)

    const int TB = 256;
    const int gN  = (NN + TB - 1) / TB;      // 196
    const int gE  = (NE + TB - 1) / TB;      // 2344
    const int gG  = (NN + 127) / 128;        // 391
    const int gW  = (NN * 32) / TB;          // 6250
    const int gPrep = (256*128 + 128*128 + 128 + 128*128 + 128 + TB - 1) / TB;

    // CSR build + weight folding
    zero_detect_kernel<<<gN, TB>>>((const int*)edge_ix);
    count_deg_kernel<<<gE, TB>>>(edge_ix);
    scan1_kernel<<<NB_SCAN, 256>>>();
    scan2_kernel<<<1, 256>>>();
    scan3_kernel<<<NB_SCAN, 256>>>();
    scatter_kernel<<<gE, TB>>>(edge_ix);
    prep_kernel<<<gPrep, TB>>>(W1, W2, W3, b1, b2, Wm, Wv, bm, bv);

    // R = h3, 64 columns at a time
    for (int c = 0; c < 128; c += 64) {
        gemmP_kernel<<<gG, TB>>>(feature, condition, P, c);
        agg64_kernel<0><<<gW, TB>>>(P, Q, nullptr, c);   // Q = A·P + bq
        agg64_kernel<1><<<gW, TB>>>(Q, R, b3, c);        // R[:,c..] = A·Q + b3
    }

    // G = A·R (fp16); (z, mean, logvar) from fused GEMM epilogue
    aggG_kernel<<<gW, TB>>>(R, G);
    gemmMV_kernel<<<gG, TB>>>(G, noise, O);
}

// round 9
// speedup vs baseline: 1.4988x; 1.0793x over previous
#include <cuda_runtime.h>
#include <cuda_fp16.h>
#include <cstdint>

// ---------------------------------------------------------------------------
// CombinedHiddenEncoder — R8: single-pass width-128, all-fp16 intermediates.
//
//   U1=W1@W3a, U2=W2@W3b, bq=b1@W3a+b2@W3b   (prep)
//   P = F@U1 + C@U2          (fp16, one FFMA2 GEMM, BN=128)
//   Q = A·P + bq             (fp16 agg)
//   R = A·Q + b3             (fp16 agg)
//   G = A·R                  (fp16 agg)
//   (mean|lv) = G@[Wm|Wv]interleaved + bcat;  z fused in GEMM epilogue
//
// d_out (O = float[9.6M]):  P=[0:3.2M) Q=[3.2M:6.4M) R=[6.4M:9.6M) all fp16
//   G over dead P; mean over dead Q; lv over dead R; z over G (own rows,
//   written after the mainloop consumed them).
// ---------------------------------------------------------------------------

#define NN 50000
#define NE 600000
#define NB_SCAN 196          // ceil(50000/256)
typedef unsigned long long ull;

// ------------------------- small device statics (~2.1 MB) ------------------
__device__ unsigned short g_src[NE];
__device__ int   g_cnt[NN];
__device__ int   g_off[NN + 1];
__device__ float g_dinv[NN];
__device__ int   g_bsum[256];
__device__ int   g_bpre[256];
__device__ float g_U1[256 * 128];         // W1@W3a
__device__ float g_U2[128 * 128];         // W2@W3b
__device__ float g_bq[128];               // b1@W3a + b2@W3b
__device__ float g_Wcat[128 * 128];       // [Wm|Wv] column-interleaved
__device__ float g_bcat[128];             // [bm|bv] interleaved
__device__ int   g_is64;

// ------------------------- f32x2 helpers -----------------------------------
__device__ __forceinline__ ull pk2(float x, float y) {
    ull r; asm("mov.b64 %0, {%1, %2};" : "=l"(r) : "f"(x), "f"(y)); return r;
}
__device__ __forceinline__ void upk2(ull v, float& x, float& y) {
    asm("mov.b64 {%0, %1}, %2;" : "=f"(x), "=f"(y) : "l"(v));
}
__device__ __forceinline__ void ffma2(ull& d, ull a, ull b) {
    asm("fma.rn.f32x2 %0, %1, %2, %0;" : "+l"(d) : "l"(a), "l"(b));
}

// ------------------------- CSR build ---------------------------------------
__global__ void zero_detect_kernel(const int* __restrict__ ei32) {
    int i = blockIdx.x * blockDim.x + threadIdx.x;
    if (i < NN) g_cnt[i] = 0;
    if (blockIdx.x == 0 && threadIdx.x < 32) {   // warp-parallel dtype detect
        int nz = 0;
        for (int k = 0; k < 16; k++) nz |= ei32[2 * (threadIdx.x * 16 + k) + 1];
        nz = __reduce_or_sync(0xffffffffu, nz);
        if (threadIdx.x == 0) g_is64 = (nz == 0) ? 1 : 0;
    }
}

__device__ __forceinline__ int edge_val(const void* ei, int idx) {
    if (g_is64) return (int)((const long long*)ei)[idx];
    return ((const int*)ei)[idx];
}

__global__ void count_deg_kernel(const void* __restrict__ ei) {
    int e = blockIdx.x * blockDim.x + threadIdx.x;
    if (e >= NE) return;
    atomicAdd(&g_cnt[edge_val(ei, NE + e)], 1);
}

__global__ void scan1_kernel() {
    __shared__ int s[256];
    int tid = threadIdx.x;
    int i = blockIdx.x * 256 + tid;
    int v = (i < NN) ? g_cnt[i] : 0;
    if (i < NN) g_dinv[i] = rsqrtf((float)(v + 1));  // +1 self loop
    s[tid] = v;
    __syncthreads();
    for (int off = 1; off < 256; off <<= 1) {
        int t = (tid >= off) ? s[tid - off] : 0;
        __syncthreads();
        s[tid] += t;
        __syncthreads();
    }
    if (i < NN) g_off[i] = s[tid];
    if (tid == 255) g_bsum[blockIdx.x] = s[255];
}

__global__ void scan2_kernel() {
    __shared__ int s[256];
    int tid = threadIdx.x;
    int v = (tid < NB_SCAN) ? g_bsum[tid] : 0;
    s[tid] = v;
    __syncthreads();
    for (int off = 1; off < 256; off <<= 1) {
        int t = (tid >= off) ? s[tid - off] : 0;
        __syncthreads();
        s[tid] += t;
        __syncthreads();
    }
    g_bpre[tid] = s[tid] - v;   // exclusive
}

__global__ void scan3_kernel() {
    int tid = threadIdx.x;
    int i = blockIdx.x * 256 + tid;
    if (i < NN) {
        g_off[i] = g_off[i] - g_cnt[i] + g_bpre[blockIdx.x];
        g_cnt[i] = 0;
    }
    if (i == 0) g_off[NN] = NE;
}

__global__ void scatter_kernel(const void* __restrict__ ei) {
    int e = blockIdx.x * blockDim.x + threadIdx.x;
    if (e >= NE) return;
    int s = edge_val(ei, e);
    int d = edge_val(ei, NE + e);
    int p = g_off[d] + atomicAdd(&g_cnt[d], 1);
    g_src[p] = (unsigned short)s;
}

// ------------------------- weight folding ----------------------------------
__global__ void prep_kernel(const float* __restrict__ W1, const float* __restrict__ W2,
                            const float* __restrict__ W3, const float* __restrict__ b1,
                            const float* __restrict__ b2,
                            const float* __restrict__ Wm, const float* __restrict__ Wv,
                            const float* __restrict__ bm, const float* __restrict__ bv) {
    int idx = blockIdx.x * blockDim.x + threadIdx.x;
    if (idx < 256 * 128) {                       // U1 = W1@W3[0:128]
        int i = idx >> 7, j = idx & 127;
        float a = 0.f;
        for (int k = 0; k < 128; k++) a += W1[i * 128 + k] * W3[k * 128 + j];
        g_U1[idx] = a;
    } else if (idx < 256 * 128 + 128 * 128) {    // U2 = W2@W3[128:256]
        int t = idx - 256 * 128;
        int i = t >> 7, j = t & 127;
        float a = 0.f;
        for (int k = 0; k < 128; k++) a += W2[i * 128 + k] * W3[(128 + k) * 128 + j];
        g_U2[t] = a;
    } else if (idx < 256 * 128 + 128 * 128 + 128) {   // bq
        int j = idx - 256 * 128 - 128 * 128;
        float a = 0.f;
        for (int k = 0; k < 128; k++)
            a += b1[k] * W3[k * 128 + j] + b2[k] * W3[(128 + k) * 128 + j];
        g_bq[j] = a;
    } else if (idx < 256 * 128 + 128 * 128 + 128 + 128 * 128) {   // Wcat interleaved
        int t = idx - 256 * 128 - 128 * 128 - 128;
        int k = t >> 7, n = t & 127;
        g_Wcat[t] = (n & 1) ? Wv[k * 64 + (n >> 1)] : Wm[k * 64 + (n >> 1)];
    } else if (idx < 256 * 128 + 128 * 128 + 128 + 128 * 128 + 128) {  // bcat
        int n = idx - 256 * 128 - 128 * 128 - 128 - 128 * 128;
        g_bcat[n] = (n & 1) ? bv[n >> 1] : bm[n >> 1];
    }
}

// ------------------------- GEMM-P: P(fp16) = F@U1 + C@U2 (BN=128) ----------
// BM=128, BN=128, BK=16; 256 threads; thread tile 8x8; FFMA2 row-pairs.
__global__ __launch_bounds__(256) void gemmP_kernel(
    const float* __restrict__ F, const float* __restrict__ C,
    __half* __restrict__ P)
{
    __shared__ float As[16][128];
    __shared__ float Bs[16][128];
    int tid = threadIdx.x;
    int tx = tid & 15, ty = tid >> 4;
    int rowBase = blockIdx.x * 128;
    ull acc[4][8];     // [row-pair p][col j]: rows (ty*8+2p, +1), col tx*8+j
#pragma unroll
    for (int p = 0; p < 4; p++)
#pragma unroll
        for (int q = 0; q < 8; q++) acc[p][q] = 0ull;

#pragma unroll
    for (int ph = 0; ph < 2; ph++) {
        const float* A = ph ? C : F;
        const float* B = ph ? g_U2 : g_U1;
        int ldA = ph ? 128 : 256;
        int K   = ph ? 128 : 256;
        for (int k0 = 0; k0 < K; k0 += 16) {
#pragma unroll
            for (int l = 0; l < 2; l++) {      // A tile transposed: As[k][row]
                int idx = tid * 2 + l;
                int r = idx >> 2, c4 = idx & 3;
                float4 v = make_float4(0.f, 0.f, 0.f, 0.f);
                int gr = rowBase + r;
                if (gr < NN) v = *(const float4*)&A[(size_t)gr * ldA + k0 + c4 * 4];
                As[c4 * 4 + 0][r] = v.x;
                As[c4 * 4 + 1][r] = v.y;
                As[c4 * 4 + 2][r] = v.z;
                As[c4 * 4 + 3][r] = v.w;
            }
#pragma unroll
            for (int l = 0; l < 2; l++) {      // B tile 16x128
                int idx = tid + l * 256;
                int r = idx >> 5, c4 = idx & 31;
                *(float4*)&Bs[r][c4 * 4] =
                    *(const float4*)&B[(size_t)(k0 + r) * 128 + c4 * 4];
            }
            __syncthreads();
#pragma unroll
            for (int k = 0; k < 16; k++) {
                const ull* ap = (const ull*)&As[k][ty * 8];
                ull a0 = ap[0], a1 = ap[1], a2 = ap[2], a3 = ap[3];
                float4 b0 = *(const float4*)&Bs[k][tx * 8];
                float4 b1 = *(const float4*)&Bs[k][tx * 8 + 4];
                ull s0 = pk2(b0.x, b0.x), s1 = pk2(b0.y, b0.y);
                ull s2 = pk2(b0.z, b0.z), s3 = pk2(b0.w, b0.w);
                ull s4 = pk2(b1.x, b1.x), s5 = pk2(b1.y, b1.y);
                ull s6 = pk2(b1.z, b1.z), s7 = pk2(b1.w, b1.w);
#pragma unroll
                for (int p = 0; p < 4; p++) {
                    ull a = (p == 0) ? a0 : (p == 1) ? a1 : (p == 2) ? a2 : a3;
                    ffma2(acc[p][0], a, s0); ffma2(acc[p][1], a, s1);
                    ffma2(acc[p][2], a, s2); ffma2(acc[p][3], a, s3);
                    ffma2(acc[p][4], a, s4); ffma2(acc[p][5], a, s5);
                    ffma2(acc[p][6], a, s6); ffma2(acc[p][7], a, s7);
                }
            }
            __syncthreads();
        }
    }
    // epilogue: fp16 store, 8 cols (16B) per row
#pragma unroll
    for (int p = 0; p < 4; p++) {
#pragma unroll
        for (int q = 0; q < 2; q++) {
            int gr = rowBase + ty * 8 + p * 2 + q;
            if (gr < NN) {
                __half2 h[4];
                float lo, hi;
#pragma unroll
                for (int j = 0; j < 4; j++) {
                    upk2(acc[p][2 * j],     lo, hi); float v0 = q ? hi : lo;
                    upk2(acc[p][2 * j + 1], lo, hi); float v1 = q ? hi : lo;
                    h[j] = __floats2half2_rn(v0, v1);
                }
                *(uint4*)&P[(size_t)gr * 128 + tx * 8] = *(uint4*)h;
            }
        }
    }
}

// ------------------------- agg width-128 fp16 -> fp16 ----------------------
// out[i] = dinv_i*(sum_j dinv_j*in[j] + dinv_i*in[i]) + bias
// mode 0: bias=g_bq; mode 1: bias=biasExt; mode 2: no bias.
__global__ __launch_bounds__(256) void agg128_kernel(
    const __half* __restrict__ in, __half* __restrict__ out,
    const float* __restrict__ biasExt, int mode)
{
    int node = (blockIdx.x * blockDim.x + threadIdx.x) >> 5;
    if (node >= NN) return;
    int lane = threadIdx.x & 31;
    float di = g_dinv[node];
    uint2 u = *(const uint2*)&in[(size_t)node * 128 + lane * 4];
    float2 t0 = __half22float2(*(__half2*)&u.x);
    float2 t1 = __half22float2(*(__half2*)&u.y);
    float a0 = di * t0.x, a1 = di * t0.y, a2 = di * t1.x, a3 = di * t1.y;
    int s = g_off[node], e = g_off[node + 1];
    for (int k = s; k < e; k++) {
        int j = g_src[k];
        float w = g_dinv[j];
        uint2 r = *(const uint2*)&in[(size_t)j * 128 + lane * 4];
        float2 r0 = __half22float2(*(__half2*)&r.x);
        float2 r1 = __half22float2(*(__half2*)&r.y);
        a0 += w * r0.x; a1 += w * r0.y; a2 += w * r1.x; a3 += w * r1.y;
    }
    float b0 = 0.f, b1 = 0.f, b2 = 0.f, b3 = 0.f;
    if (mode == 0) {
        b0 = g_bq[lane * 4]; b1 = g_bq[lane * 4 + 1];
        b2 = g_bq[lane * 4 + 2]; b3 = g_bq[lane * 4 + 3];
    } else if (mode == 1) {
        b0 = biasExt[lane * 4]; b1 = biasExt[lane * 4 + 1];
        b2 = biasExt[lane * 4 + 2]; b3 = biasExt[lane * 4 + 3];
    }
    uint2 o;
    *(__half2*)&o.x = __floats2half2_rn(a0 * di + b0, a1 * di + b1);
    *(__half2*)&o.y = __floats2half2_rn(a2 * di + b2, a3 * di + b3);
    *(uint2*)&out[(size_t)node * 128 + lane * 4] = o;
}

// ------------------------- GEMM-MV + fused reparam -------------------------
// (mean|lv interleaved) = G@Wcat + bcat; z = noise*exp(.5lv)+mean in epilogue.
__global__ __launch_bounds__(256) void gemmMV_kernel(
    const __half* __restrict__ G, const float* __restrict__ noise,
    float* __restrict__ O)
{
    __shared__ float As[16][128];
    __shared__ float Bs[16][128];
    int tid = threadIdx.x;
    int tx = tid & 15, ty = tid >> 4;
    int rowBase = blockIdx.x * 128;
    ull acc[4][8];
#pragma unroll
    for (int p = 0; p < 4; p++)
#pragma unroll
        for (int q = 0; q < 8; q++) acc[p][q] = 0ull;

    for (int k0 = 0; k0 < 128; k0 += 16) {
        {   // A tile fp16: 2 threads per row, 8 halves each, transposed
            int r = tid >> 1;
            int hb = (tid & 1) * 8;
            int gr = rowBase + r;
            uint4 u = make_uint4(0u, 0u, 0u, 0u);
            if (gr < NN) u = *(const uint4*)&G[(size_t)gr * 128 + k0 + hb];
            const __half2* hp = (const __half2*)&u;
#pragma unroll
            for (int q = 0; q < 4; q++) {
                float2 f = __half22float2(hp[q]);
                As[hb + q * 2 + 0][r] = f.x;
                As[hb + q * 2 + 1][r] = f.y;
            }
        }
#pragma unroll
        for (int l = 0; l < 2; l++) {          // B tile
            int idx = tid + l * 256;
            int r = idx >> 5, c4 = idx & 31;
            *(float4*)&Bs[r][c4 * 4] =
                *(const float4*)&g_Wcat[(size_t)(k0 + r) * 128 + c4 * 4];
        }
        __syncthreads();
#pragma unroll
        for (int k = 0; k < 16; k++) {
            const ull* ap = (const ull*)&As[k][ty * 8];
            ull a0 = ap[0], a1 = ap[1], a2 = ap[2], a3 = ap[3];
            float4 b0 = *(const float4*)&Bs[k][tx * 8];
            float4 b1 = *(const float4*)&Bs[k][tx * 8 + 4];
            ull s0 = pk2(b0.x, b0.x), s1 = pk2(b0.y, b0.y);
            ull s2 = pk2(b0.z, b0.z), s3 = pk2(b0.w, b0.w);
            ull s4 = pk2(b1.x, b1.x), s5 = pk2(b1.y, b1.y);
            ull s6 = pk2(b1.z, b1.z), s7 = pk2(b1.w, b1.w);
#pragma unroll
            for (int p = 0; p < 4; p++) {
                ull a = (p == 0) ? a0 : (p == 1) ? a1 : (p == 2) ? a2 : a3;
                ffma2(acc[p][0], a, s0); ffma2(acc[p][1], a, s1);
                ffma2(acc[p][2], a, s2); ffma2(acc[p][3], a, s3);
                ffma2(acc[p][4], a, s4); ffma2(acc[p][5], a, s5);
                ffma2(acc[p][6], a, s6); ffma2(acc[p][7], a, s7);
            }
        }
        __syncthreads();
    }
    // epilogue: cols tx*8+2j = mean latent (tx*4+j), +1 = logvar; fuse reparam.
    int n0 = tx * 8;
#pragma unroll
    for (int p = 0; p < 4; p++) {
#pragma unroll
        for (int q = 0; q < 2; q++) {
            int gr = rowBase + ty * 8 + p * 2 + q;
            if (gr < NN) {
                float4 mean, lv;
                float lo, hi;
#define GETV(j, mdst, ldst)                                                   \
                upk2(acc[p][2*(j)],   lo, hi); mdst = (q ? hi : lo) + g_bcat[n0 + 2*(j)]; \
                upk2(acc[p][2*(j)+1], lo, hi); ldst = (q ? hi : lo) + g_bcat[n0 + 2*(j)+1];
                GETV(0, mean.x, lv.x) GETV(1, mean.y, lv.y)
                GETV(2, mean.z, lv.z) GETV(3, mean.w, lv.w)
#undef GETV
                float4 nz = *(const float4*)&noise[(size_t)gr * 64 + tx * 4];
                float4 z;
                z.x = nz.x * expf(0.5f * lv.x) + mean.x;
                z.y = nz.y * expf(0.5f * lv.y) + mean.y;
                z.z = nz.z * expf(0.5f * lv.z) + mean.z;
                z.w = nz.w * expf(0.5f * lv.w) + mean.w;
                size_t o = (size_t)gr * 64 + tx * 4;
                *(float4*)&O[o] = z;                    // over own (dead) G rows
                *(float4*)&O[3200000 + o] = mean;
                *(float4*)&O[6400000 + o] = lv;
            }
        }
    }
}

// ------------------------- host launcher -----------------------------------
extern "C" void kernel_launch(void* const* d_in, const int* in_sizes, int n_in,
                              void* d_out, int out_size)
{
    const float* feature   = (const float*)d_in[0];
    const float* condition = (const float*)d_in[1];
    const void*  edge_ix   = d_in[2];
    const float* noise     = (const float*)d_in[3];
    const float* W1 = (const float*)d_in[4];
    const float* b1 = (const float*)d_in[5];
    const float* W2 = (const float*)d_in[6];
    const float* b2 = (const float*)d_in[7];
    const float* W3 = (const float*)d_in[8];
    const float* b3 = (const float*)d_in[9];
    const float* Wm = (const float*)d_in[10];
    const float* bm = (const float*)d_in[11];
    const float* Wv = (const float*)d_in[12];
    const float* bv = (const float*)d_in[13];
    float* O = (float*)d_out;

    __half* P = (__half*)O;               // 50k x 128 fp16 [0 : 3.2M floats)
    __half* Q = (__half*)(O + 3200000);   // 50k x 128 fp16 [3.2M : 6.4M)
    __half* R = (__half*)(O + 6400000);   // 50k x 128 fp16 [6.4M : 9.6M)
    __half* G = (__half*)O;               // over dead P

    const int TB = 256;
    const int gN  = (NN + TB - 1) / TB;      // 196
    const int gE  = (NE + TB - 1) / TB;      // 2344
    const int gG  = (NN + 127) / 128;        // 391
    const int gW  = (NN * 32) / TB;          // 6250
    const int gPrep = (256*128 + 128*128 + 128 + 128*128 + 128 + TB - 1) / TB;

    // CSR build + weight folding
    zero_detect_kernel<<<gN, TB>>>((const int*)edge_ix);
    count_deg_kernel<<<gE, TB>>>(edge_ix);
    scan1_kernel<<<NB_SCAN, 256>>>();
    scan2_kernel<<<1, 256>>>();
    scan3_kernel<<<NB_SCAN, 256>>>();
    scatter_kernel<<<gE, TB>>>(edge_ix);
    prep_kernel<<<gPrep, TB>>>(W1, W2, W3, b1, b2, Wm, Wv, bm, bv);

    // dense front: P = F@U1 + C@U2
    gemmP_kernel<<<gG, TB>>>(feature, condition, P);

    // three aggregations
    agg128_kernel<<<gW, TB>>>(P, Q, nullptr, 0);   // Q = A·P + bq
    agg128_kernel<<<gW, TB>>>(Q, R, b3, 1);        // R = A·Q + b3
    agg128_kernel<<<gW, TB>>>(R, G, nullptr, 2);   // G = A·R

    // final GEMM + fused reparam
    gemmMV_kernel<<<gG, TB>>>(G, noise, O);
}

// round 12
// speedup vs baseline: 2.4164x; 1.6122x over previous
#include <cuda_runtime.h>
#include <cuda_fp16.h>
#include <cstdint>

// ---------------------------------------------------------------------------
// CombinedHiddenEncoder — R11: HMMA GEMMs. Fix vs R10: gemmP B-stage reads
// g_UT at the GLOBAL k offset (s*64), while the A-stage keeps the per-matrix
// local offset — stages 4-5 (condition phase) now hit U2, not U1.
//
//   prep: g_UT[n][k] fp16 = [U1;U2]^T (U1=W1@W3a, U2=W2@W3b), bq,
//         g_WcatTH[n][k] fp16 = [Wm|Wv]-interleaved^T, bcat
//   P = [F|C]@UT^T          (fp16 out, HMMA)
//   Q = A·P + bq ; R = A·Q + b3 ; G = A·R     (fp16 aggs)
//   (mean|lv) = G@WcatTH^T + bcat; z fused in epilogue (HMMA)
//
// d_out (O = float[9.6M]): P=[0:3.2M) Q=[3.2M:6.4M) R=[6.4M:9.6M) fp16;
//   G over dead P; z over own G rows; mean over dead Q; lv over dead R.
// ---------------------------------------------------------------------------

#define NN 50000
#define NE 600000
#define NB_SCAN 196

// ------------------------- device statics (~1.5 MB) ------------------------
__device__ unsigned short g_src[NE];
__device__ int    g_cnt[NN];
__device__ int    g_off[NN + 1];
__device__ float  g_dinv[NN];
__device__ int    g_bsum[256];
__device__ int    g_bpre[256];
__device__ __half g_UT[128 * 384];        // [n][k] fp16, k<256 from U1, rest U2
__device__ float  g_bq[128];
__device__ __half g_WcatTH[128 * 128];    // [n][k] fp16, n interleaved (e=Wm,o=Wv)
__device__ float  g_bcat[128];            // interleaved [bm|bv]
__device__ int    g_is64;

// ------------------------- mma helpers -------------------------------------
__device__ __forceinline__ uint32_t s2u(const void* p) {
    return (uint32_t)__cvta_generic_to_shared(p);
}
__device__ __forceinline__ void ldsm_x4(uint32_t addr, uint32_t& r0, uint32_t& r1,
                                        uint32_t& r2, uint32_t& r3) {
    asm volatile("ldmatrix.sync.aligned.m8n8.x4.shared.b16 {%0,%1,%2,%3}, [%4];"
                 : "=r"(r0), "=r"(r1), "=r"(r2), "=r"(r3) : "r"(addr));
}
__device__ __forceinline__ void mma16816(float* c, const uint32_t* a,
                                         uint32_t b0, uint32_t b1) {
    asm volatile(
        "mma.sync.aligned.m16n8k16.row.col.f32.f16.f16.f32 "
        "{%0,%1,%2,%3}, {%4,%5,%6,%7}, {%8,%9}, {%0,%1,%2,%3};"
        : "+f"(c[0]), "+f"(c[1]), "+f"(c[2]), "+f"(c[3])
        : "r"(a[0]), "r"(a[1]), "r"(a[2]), "r"(a[3]), "r"(b0), "r"(b1));
}

// ------------------------- CSR build ---------------------------------------
__global__ void zero_detect_kernel(const int* __restrict__ ei32) {
    int i = blockIdx.x * blockDim.x + threadIdx.x;
    if (i < NN) g_cnt[i] = 0;
    if (blockIdx.x == 0 && threadIdx.x < 32) {
        int nz = 0;
        for (int k = 0; k < 16; k++) nz |= ei32[2 * (threadIdx.x * 16 + k) + 1];
        nz = __reduce_or_sync(0xffffffffu, nz);
        if (threadIdx.x == 0) g_is64 = (nz == 0) ? 1 : 0;
    }
}

__device__ __forceinline__ int edge_val(const void* ei, int idx) {
    if (g_is64) return (int)((const long long*)ei)[idx];
    return ((const int*)ei)[idx];
}

__global__ void count_deg_kernel(const void* __restrict__ ei) {
    int e = blockIdx.x * blockDim.x + threadIdx.x;
    if (e >= NE) return;
    atomicAdd(&g_cnt[edge_val(ei, NE + e)], 1);
}

__global__ void scan1_kernel() {
    __shared__ int s[256];
    int tid = threadIdx.x;
    int i = blockIdx.x * 256 + tid;
    int v = (i < NN) ? g_cnt[i] : 0;
    if (i < NN) g_dinv[i] = rsqrtf((float)(v + 1));
    s[tid] = v;
    __syncthreads();
    for (int off = 1; off < 256; off <<= 1) {
        int t = (tid >= off) ? s[tid - off] : 0;
        __syncthreads();
        s[tid] += t;
        __syncthreads();
    }
    if (i < NN) g_off[i] = s[tid];
    if (tid == 255) g_bsum[blockIdx.x] = s[255];
}

__global__ void scan2_kernel() {
    __shared__ int s[256];
    int tid = threadIdx.x;
    int v = (tid < NB_SCAN) ? g_bsum[tid] : 0;
    s[tid] = v;
    __syncthreads();
    for (int off = 1; off < 256; off <<= 1) {
        int t = (tid >= off) ? s[tid - off] : 0;
        __syncthreads();
        s[tid] += t;
        __syncthreads();
    }
    g_bpre[tid] = s[tid] - v;
}

__global__ void scan3_kernel() {
    int tid = threadIdx.x;
    int i = blockIdx.x * 256 + tid;
    if (i < NN) {
        g_off[i] = g_off[i] - g_cnt[i] + g_bpre[blockIdx.x];
        g_cnt[i] = 0;
    }
    if (i == 0) g_off[NN] = NE;
}

__global__ void scatter_kernel(const void* __restrict__ ei) {
    int e = blockIdx.x * blockDim.x + threadIdx.x;
    if (e >= NE) return;
    int s = edge_val(ei, e);
    int d = edge_val(ei, NE + e);
    int p = g_off[d] + atomicAdd(&g_cnt[d], 1);
    g_src[p] = (unsigned short)s;
}

// ------------------------- weight folding ----------------------------------
__global__ void prep_kernel(const float* __restrict__ W1, const float* __restrict__ W2,
                            const float* __restrict__ W3, const float* __restrict__ b1,
                            const float* __restrict__ b2,
                            const float* __restrict__ Wm, const float* __restrict__ Wv,
                            const float* __restrict__ bm, const float* __restrict__ bv) {
    int idx = blockIdx.x * blockDim.x + threadIdx.x;
    if (idx < 49152) {                             // g_UT[n][k]
        int n = idx / 384, k = idx % 384;
        float a = 0.f;
        if (k < 256) {
            for (int j = 0; j < 128; j++) a += W1[k * 128 + j] * W3[j * 128 + n];
        } else {
            int kc = k - 256;
            for (int j = 0; j < 128; j++) a += W2[kc * 128 + j] * W3[(128 + j) * 128 + n];
        }
        g_UT[n * 384 + k] = __float2half_rn(a);
    } else if (idx < 49280) {                      // bq
        int n = idx - 49152;
        float a = 0.f;
        for (int j = 0; j < 128; j++)
            a += b1[j] * W3[j * 128 + n] + b2[j] * W3[(128 + j) * 128 + n];
        g_bq[n] = a;
    } else if (idx < 65664) {                      // g_WcatTH[n][k]
        int t = idx - 49280;
        int n = t >> 7, k = t & 127;
        float v = (n & 1) ? Wv[k * 64 + (n >> 1)] : Wm[k * 64 + (n >> 1)];
        g_WcatTH[n * 128 + k] = __float2half_rn(v);
    } else if (idx < 65792) {                      // bcat interleaved
        int n = idx - 65664;
        g_bcat[n] = (n & 1) ? bv[n >> 1] : bm[n >> 1];
    }
}

// ------------------------- GEMM-P (HMMA): P(fp16) = [F|C]@UT^T -------------
// BM=128, BN=128, BK=64 staged; 8 warps (4m x 2n), warp tile 32x64.
__global__ __launch_bounds__(256) void gemmP_kernel(
    const float* __restrict__ F, const float* __restrict__ C,
    __half* __restrict__ P)
{
    __shared__ __align__(16) __half As[128 * 72];
    __shared__ __align__(16) __half Bs[128 * 72];
    int tid = threadIdx.x, lane = tid & 31, wid = tid >> 5;
    int wm = (wid & 3) * 32, wn = (wid >> 2) * 64;
    int rowBase = blockIdx.x * 128;
    float c[2][8][4];
#pragma unroll
    for (int mt = 0; mt < 2; mt++)
#pragma unroll
        for (int j = 0; j < 8; j++)
#pragma unroll
            for (int q = 0; q < 4; q++) c[mt][j][q] = 0.f;

    for (int s = 0; s < 6; s++) {
        const float* A = (s < 4) ? F : C;
        int ldA = (s < 4) ? 256 : 128;
        int kb  = (s < 4) ? s * 64 : (s - 4) * 64;   // A-local k offset
        int kbB = s * 64;                             // GLOBAL k offset into UT
        // A stage: 128 x 64 fp32 -> fp16 smem (stride 72); 2048 float4
#pragma unroll
        for (int l = 0; l < 8; l++) {
            int fid = tid + l * 256;
            int r = fid >> 4, c4 = fid & 15;
            int gr = rowBase + r;
            float4 v = make_float4(0.f, 0.f, 0.f, 0.f);
            if (gr < NN) v = *(const float4*)&A[(size_t)gr * ldA + kb + c4 * 4];
            __half2 h0 = __floats2half2_rn(v.x, v.y);
            __half2 h1 = __floats2half2_rn(v.z, v.w);
            uint2 u = make_uint2(*(uint32_t*)&h0, *(uint32_t*)&h1);
            *(uint2*)&As[r * 72 + c4 * 4] = u;
        }
        // B stage: g_UT[n][kbB..kbB+64) — 1024 uint4 (128 n x 8 uint4)
#pragma unroll
        for (int l = 0; l < 4; l++) {
            int hid = tid + l * 256;
            int n = hid >> 3, c8 = hid & 7;
            *(uint4*)&Bs[n * 72 + c8 * 8] = *(const uint4*)&g_UT[n * 384 + kbB + c8 * 8];
        }
        __syncthreads();
#pragma unroll
        for (int kk = 0; kk < 4; kk++) {
            uint32_t a[2][4], b[4][4];
#pragma unroll
            for (int mt = 0; mt < 2; mt++) {
                int row = wm + mt * 16 + (lane & 7) + 8 * ((lane >> 3) & 1);
                int col = kk * 16 + 8 * (lane >> 4);
                ldsm_x4(s2u(&As[row * 72 + col]), a[mt][0], a[mt][1], a[mt][2], a[mt][3]);
            }
#pragma unroll
            for (int jp = 0; jp < 4; jp++) {
                int row = wn + jp * 16 + (lane & 7) + 8 * (lane >> 4);
                int col = kk * 16 + 8 * ((lane >> 3) & 1);
                ldsm_x4(s2u(&Bs[row * 72 + col]), b[jp][0], b[jp][1], b[jp][2], b[jp][3]);
            }
#pragma unroll
            for (int mt = 0; mt < 2; mt++)
#pragma unroll
                for (int jp = 0; jp < 4; jp++) {
                    mma16816(c[mt][jp * 2],     a[mt], b[jp][0], b[jp][1]);
                    mma16816(c[mt][jp * 2 + 1], a[mt], b[jp][2], b[jp][3]);
                }
        }
        __syncthreads();
    }
    // epilogue: fp16 store (c0,c1)=(col n, n+1) per thread
#pragma unroll
    for (int mt = 0; mt < 2; mt++)
#pragma unroll
        for (int j = 0; j < 8; j++) {
            int r0 = rowBase + wm + mt * 16 + (lane >> 2);
            int n  = wn + j * 8 + 2 * (lane & 3);
            if (r0 < NN)
                *(__half2*)&P[(size_t)r0 * 128 + n] =
                    __floats2half2_rn(c[mt][j][0], c[mt][j][1]);
            int r1 = r0 + 8;
            if (r1 < NN)
                *(__half2*)&P[(size_t)r1 * 128 + n] =
                    __floats2half2_rn(c[mt][j][2], c[mt][j][3]);
        }
}

// ------------------------- agg width-128 fp16 -> fp16 ----------------------
__global__ __launch_bounds__(256) void agg128_kernel(
    const __half* __restrict__ in, __half* __restrict__ out,
    const float* __restrict__ biasExt, int mode)
{
    int node = (blockIdx.x * blockDim.x + threadIdx.x) >> 5;
    if (node >= NN) return;
    int lane = threadIdx.x & 31;
    float di = g_dinv[node];
    uint2 u = *(const uint2*)&in[(size_t)node * 128 + lane * 4];
    float2 t0 = __half22float2(*(__half2*)&u.x);
    float2 t1 = __half22float2(*(__half2*)&u.y);
    float a0 = di * t0.x, a1 = di * t0.y, a2 = di * t1.x, a3 = di * t1.y;
    int s = g_off[node], e = g_off[node + 1];
    for (int k = s; k < e; k++) {
        int j = g_src[k];
        float w = g_dinv[j];
        uint2 r = *(const uint2*)&in[(size_t)j * 128 + lane * 4];
        float2 r0 = __half22float2(*(__half2*)&r.x);
        float2 r1 = __half22float2(*(__half2*)&r.y);
        a0 += w * r0.x; a1 += w * r0.y; a2 += w * r1.x; a3 += w * r1.y;
    }
    float b0 = 0.f, b1 = 0.f, b2 = 0.f, b3 = 0.f;
    if (mode == 0) {
        b0 = g_bq[lane * 4]; b1 = g_bq[lane * 4 + 1];
        b2 = g_bq[lane * 4 + 2]; b3 = g_bq[lane * 4 + 3];
    } else if (mode == 1) {
        b0 = biasExt[lane * 4]; b1 = biasExt[lane * 4 + 1];
        b2 = biasExt[lane * 4 + 2]; b3 = biasExt[lane * 4 + 3];
    }
    uint2 o;
    *(__half2*)&o.x = __floats2half2_rn(a0 * di + b0, a1 * di + b1);
    *(__half2*)&o.y = __floats2half2_rn(a2 * di + b2, a3 * di + b3);
    *(uint2*)&out[(size_t)node * 128 + lane * 4] = o;
}

// ------------------------- GEMM-MV (HMMA) + fused reparam ------------------
__global__ __launch_bounds__(256) void gemmMV_kernel(
    const __half* __restrict__ G, const float* __restrict__ noise,
    float* __restrict__ O)
{
    __shared__ __align__(16) __half As[128 * 72];
    __shared__ __align__(16) __half Bs[128 * 72];
    int tid = threadIdx.x, lane = tid & 31, wid = tid >> 5;
    int wm = (wid & 3) * 32, wn = (wid >> 2) * 64;
    int rowBase = blockIdx.x * 128;
    float c[2][8][4];
#pragma unroll
    for (int mt = 0; mt < 2; mt++)
#pragma unroll
        for (int j = 0; j < 8; j++)
#pragma unroll
            for (int q = 0; q < 4; q++) c[mt][j][q] = 0.f;

    for (int s = 0; s < 2; s++) {
        int kb = s * 64;
        // A stage: G rows fp16 — 1024 uint4
#pragma unroll
        for (int l = 0; l < 4; l++) {
            int hid = tid + l * 256;
            int r = hid >> 3, c8 = hid & 7;
            int gr = rowBase + r;
            uint4 u = make_uint4(0u, 0u, 0u, 0u);
            if (gr < NN) u = *(const uint4*)&G[(size_t)gr * 128 + kb + c8 * 8];
            *(uint4*)&As[r * 72 + c8 * 8] = u;
        }
        // B stage — 1024 uint4
#pragma unroll
        for (int l = 0; l < 4; l++) {
            int hid = tid + l * 256;
            int n = hid >> 3, c8 = hid & 7;
            *(uint4*)&Bs[n * 72 + c8 * 8] = *(const uint4*)&g_WcatTH[n * 128 + kb + c8 * 8];
        }
        __syncthreads();
#pragma unroll
        for (int kk = 0; kk < 4; kk++) {
            uint32_t a[2][4], b[4][4];
#pragma unroll
            for (int mt = 0; mt < 2; mt++) {
                int row = wm + mt * 16 + (lane & 7) + 8 * ((lane >> 3) & 1);
                int col = kk * 16 + 8 * (lane >> 4);
                ldsm_x4(s2u(&As[row * 72 + col]), a[mt][0], a[mt][1], a[mt][2], a[mt][3]);
            }
#pragma unroll
            for (int jp = 0; jp < 4; jp++) {
                int row = wn + jp * 16 + (lane & 7) + 8 * (lane >> 4);
                int col = kk * 16 + 8 * ((lane >> 3) & 1);
                ldsm_x4(s2u(&Bs[row * 72 + col]), b[jp][0], b[jp][1], b[jp][2], b[jp][3]);
            }
#pragma unroll
            for (int mt = 0; mt < 2; mt++)
#pragma unroll
                for (int jp = 0; jp < 4; jp++) {
                    mma16816(c[mt][jp * 2],     a[mt], b[jp][0], b[jp][1]);
                    mma16816(c[mt][jp * 2 + 1], a[mt], b[jp][2], b[jp][3]);
                }
        }
        __syncthreads();
    }
    // epilogue: c0=mean(r0,L), c1=lv(r0,L); c2/c3 for r0+8; fused reparam.
#pragma unroll
    for (int mt = 0; mt < 2; mt++)
#pragma unroll
        for (int j = 0; j < 8; j++) {
            int nabs = wn + j * 8 + 2 * (lane & 3);
            int L = nabs >> 1;
            float bm_ = g_bcat[nabs], bv_ = g_bcat[nabs + 1];
#pragma unroll
            for (int h = 0; h < 2; h++) {
                int r = rowBase + wm + mt * 16 + (lane >> 2) + h * 8;
                if (r < NN) {
                    float mean = c[mt][j][h * 2]     + bm_;
                    float lv   = c[mt][j][h * 2 + 1] + bv_;
                    size_t o = (size_t)r * 64 + L;
                    float z = noise[o] * expf(0.5f * lv) + mean;
                    O[o] = z;                    // over own (dead) G rows
                    O[3200000 + o] = mean;
                    O[6400000 + o] = lv;
                }
            }
        }
}

// ------------------------- host launcher -----------------------------------
extern "C" void kernel_launch(void* const* d_in, const int* in_sizes, int n_in,
                              void* d_out, int out_size)
{
    const float* feature   = (const float*)d_in[0];
    const float* condition = (const float*)d_in[1];
    const void*  edge_ix   = d_in[2];
    const float* noise     = (const float*)d_in[3];
    const float* W1 = (const float*)d_in[4];
    const float* b1 = (const float*)d_in[5];
    const float* W2 = (const float*)d_in[6];
    const float* b2 = (const float*)d_in[7];
    const float* W3 = (const float*)d_in[8];
    const float* b3 = (const float*)d_in[9];
    const float* Wm = (const float*)d_in[10];
    const float* bm = (const float*)d_in[11];
    const float* Wv = (const float*)d_in[12];
    const float* bv = (const float*)d_in[13];
    float* O = (float*)d_out;

    __half* P = (__half*)O;               // [0 : 3.2M floats) fp16
    __half* Q = (__half*)(O + 3200000);
    __half* R = (__half*)(O + 6400000);
    __half* G = (__half*)O;               // over dead P

    const int TB = 256;
    const int gN  = (NN + TB - 1) / TB;
    const int gE  = (NE + TB - 1) / TB;
    const int gG  = (NN + 127) / 128;        // 391
    const int gW  = (NN * 32) / TB;          // 6250
    const int gPrep = (65792 + TB - 1) / TB; // 257

    zero_detect_kernel<<<gN, TB>>>((const int*)edge_ix);
    count_deg_kernel<<<gE, TB>>>(edge_ix);
    scan1_kernel<<<NB_SCAN, 256>>>();
    scan2_kernel<<<1, 256>>>();
    scan3_kernel<<<NB_SCAN, 256>>>();
    scatter_kernel<<<gE, TB>>>(edge_ix);
    prep_kernel<<<gPrep, TB>>>(W1, W2, W3, b1, b2, Wm, Wv, bm, bv);

    gemmP_kernel<<<gG, TB>>>(feature, condition, P);

    agg128_kernel<<<gW, TB>>>(P, Q, nullptr, 0);   // Q = A·P + bq
    agg128_kernel<<<gW, TB>>>(Q, R, b3, 1);        // R = A·Q + b3
    agg128_kernel<<<gW, TB>>>(R, G, nullptr, 2);   // G = A·R

    gemmMV_kernel<<<gG, TB>>>(G, noise, O);
}